// round 12
// baseline (speedup 1.0000x reference)
#include <cuda_runtime.h>
#include <cuda_bf16.h>
#include <cstdint>

// Problem dims
#define B_DIM 256
#define S_DIM 512
#define I_DIM 64
#define H_DIM 256

#define CLUSTER 8
#define GBATCH 16
#define HSLICE 32
#define NTHREADS 256      // 8 warps

// Weights: [2 half][320 k][128 n] bf16, pitch 272B (conflict-free LDSM)
#define WPITCH 272
#define OFF_W   0
#define WHALF   (320 * WPITCH)            // 87040
// A x-panel: [2 buf][2 half][64 k][16 b] bf16
#define OFF_AX  (2 * WHALF)               // 174080
#define AXBUF   4096
// A h-panel: [2 buf][2 half][256 k][16 b] bf16
#define OFF_AH  (OFF_AX + 2 * AXBUF)      // 182272
#define AHBUF   16384
// h staging for compact pushes: [32 hd][2 half][16 b] bf16 = 2KB
#define OFF_HSTG (OFF_AH + 2 * AHBUF)     // 215040
// join mbarrier (8B, padded to 64)
#define OFF_MBAR (OFF_HSTG + 2048)        // 217088
#define SMEM_BYTES (OFF_MBAR + 64)        // 217152

__device__ __forceinline__ float sigf(float x) {
    return __fdividef(1.0f, 1.0f + __expf(-x));
}
__device__ __forceinline__ float tanh_(float x) {
    return __fdividef(2.0f, 1.0f + __expf(-2.0f * x)) - 1.0f;
}

__device__ __forceinline__ uint32_t smem_u32(const void* p) {
    uint32_t a;
    asm("{ .reg .u64 t; cvta.to.shared.u64 t, %1; cvt.u32.u64 %0, t; }" : "=r"(a) : "l"(p));
    return a;
}
__device__ __forceinline__ uint32_t mapa_u32(uint32_t addr, uint32_t rank) {
    uint32_t r;
    asm("mapa.shared::cluster.u32 %0, %1, %2;" : "=r"(r) : "r"(addr), "r"(rank));
    return r;
}
__device__ __forceinline__ void stc128(uint32_t addr, uint4 v) {
    asm volatile("st.shared::cluster.v4.b32 [%0], {%1,%2,%3,%4};"
                 :: "r"(addr), "r"(v.x), "r"(v.y), "r"(v.z), "r"(v.w) : "memory");
}
#define CLUSTER_SYNC() do { \
    asm volatile("barrier.cluster.arrive.aligned;" ::: "memory"); \
    asm volatile("barrier.cluster.wait.aligned;" ::: "memory"); \
} while (0)

// mbarrier ops
#define MBAR_INIT(a, c) \
    asm volatile("mbarrier.init.shared.b64 [%0], %1;" :: "r"(a), "r"(c) : "memory")
#define MBAR_ARRIVE_LOCAL_CNT(a, c) \
    asm volatile("mbarrier.arrive.shared::cta.b64 _, [%0], %1;" :: "r"(a), "r"(c) : "memory")
#define MBAR_ARRIVE_REMOTE(a) \
    asm volatile("mbarrier.arrive.release.cluster.shared::cluster.b64 _, [%0];" \
                 :: "r"(a) : "memory")
#define MBAR_WAIT_CLUSTER(a, ph) do { \
    uint32_t _m = (a), _p = (ph), _d; \
    asm volatile("{\n\t.reg .pred p;\n\t" \
        "mbarrier.try_wait.parity.acquire.cluster.shared::cta.b64 p, [%1], %2;\n\t" \
        "selp.b32 %0, 1, 0, p;\n\t}" : "=r"(_d) : "r"(_m), "r"(_p) : "memory"); \
    if (!_d) { \
        asm volatile("{\n\t.reg .pred P1;\n\t" \
            "WL_%=:\n\t" \
            "mbarrier.try_wait.parity.acquire.cluster.shared::cta.b64 P1, [%0], %1, 0x989680;\n\t" \
            "@P1 bra.uni WD_%=;\n\t" \
            "bra.uni WL_%=;\n\t" \
            "WD_%=:\n\t}" :: "r"(_m), "r"(_p) : "memory"); \
    } \
} while (0)

#define LDSM4T(r0, r1, r2, r3, addr) \
    asm volatile("ldmatrix.sync.aligned.m8n8.x4.trans.shared.b16 {%0,%1,%2,%3}, [%4];" \
                 : "=r"(r0), "=r"(r1), "=r"(r2), "=r"(r3) : "r"(addr))

#define MMA(d0, d1, d2, d3, a0, a1, a2, a3, b0, b1) \
    asm volatile("mma.sync.aligned.m16n8k16.row.col.f32.bf16.bf16.f32 " \
                 "{%0,%1,%2,%3}, {%4,%5,%6,%7}, {%8,%9}, {%0,%1,%2,%3};" \
                 : "+f"(d0), "+f"(d1), "+f"(d2), "+f"(d3) \
                 : "r"(a0), "r"(a1), "r"(a2), "r"(a3), "r"(b0), "r"(b1))

__device__ __forceinline__ void bfsplit(float v, uint16_t& hi, uint16_t& lo) {
    __nv_bfloat16 h = __float2bfloat16(v);
    float r = v - __bfloat162float(h);
    __nv_bfloat16 l = __float2bfloat16(r);
    hi = *reinterpret_cast<uint16_t*>(&h);
    lo = *reinterpret_cast<uint16_t*>(&l);
}

// 6 MMAs per k-step, 3 INDEPENDENT accumulator chains x 2 n-tiles
#define MMA6S(AH, AL, BH, BL) do { \
    MMA(aA[0][0], aA[0][1], aA[0][2], aA[0][3], (AH)[0], (AH)[1], (AH)[2], (AH)[3], (BH)[0], (BH)[1]); \
    MMA(aB[0][0], aB[0][1], aB[0][2], aB[0][3], (AH)[0], (AH)[1], (AH)[2], (AH)[3], (BL)[0], (BL)[1]); \
    MMA(aC[0][0], aC[0][1], aC[0][2], aC[0][3], (AL)[0], (AL)[1], (AL)[2], (AL)[3], (BH)[0], (BH)[1]); \
    MMA(aA[1][0], aA[1][1], aA[1][2], aA[1][3], (AH)[0], (AH)[1], (AH)[2], (AH)[3], (BH)[2], (BH)[3]); \
    MMA(aB[1][0], aB[1][1], aB[1][2], aB[1][3], (AH)[0], (AH)[1], (AH)[2], (AH)[3], (BL)[2], (BL)[3]); \
    MMA(aC[1][0], aC[1][1], aC[1][2], aC[1][3], (AL)[0], (AL)[1], (AL)[2], (AL)[3], (BH)[2], (BH)[3]); \
} while (0)

// A-only k-step load (hi + lo halves); ALOFF = 2048 (x panel) or 8192 (h panel)
#define LOADA(S, AADDR, ALOFF) do { \
    LDSM4T(fah[S][0], fah[S][1], fah[S][2], fah[S][3], (AADDR)); \
    LDSM4T(fal[S][0], fal[S][1], fal[S][2], fal[S][3], (AADDR) + (ALOFF)); \
} while (0)

__global__ void __cluster_dims__(CLUSTER, 1, 1) __launch_bounds__(NTHREADS, 1)
lstm_hmma(const float* __restrict__ x,
          const float* __restrict__ w_i, const float* __restrict__ u_i, const float* __restrict__ b_i,
          const float* __restrict__ w_f, const float* __restrict__ u_f, const float* __restrict__ b_f,
          const float* __restrict__ w_c, const float* __restrict__ u_c, const float* __restrict__ b_c,
          const float* __restrict__ w_o, const float* __restrict__ u_o, const float* __restrict__ b_o,
          float* __restrict__ out)
{
    extern __shared__ char smem[];
    const uint32_t sb = smem_u32(smem);
    const int tid  = threadIdx.x;
    const int lane = tid & 31;
    const int warp = tid >> 5;

    uint32_t rank;
    asm("mov.u32 %0, %%cluster_ctarank;" : "=r"(rank));
    const int gb   = (blockIdx.x / CLUSTER) * GBATCH;
    const int colh = (int)rank * HSLICE;

    // ---- join mbarrier init (count = 8: one arrival per cluster CTA per phase) ----
    const uint32_t mbar = sb + OFF_MBAR;
    if (tid == 0) MBAR_INIT(mbar, 8);

    // ---- stage weights to smem (once): W[half][k][n], n = 4*hd + g, bf16 hi/lo ----
    #pragma unroll
    for (int g = 0; g < 4; ++g) {
        const float* Wsrc = (g == 0) ? w_i : (g == 1) ? w_f : (g == 2) ? w_c : w_o;
        const float* Usrc = (g == 0) ? u_i : (g == 1) ? u_f : (g == 2) ? u_c : u_o;
        for (int k = warp; k < 320; k += 8) {
            const float* src = (k < I_DIM) ? (Wsrc + (size_t)k * H_DIM)
                                           : (Usrc + (size_t)(k - I_DIM) * H_DIM);
            float v = src[colh + lane];
            uint16_t hi, lo;
            bfsplit(v, hi, lo);
            uint32_t o = (uint32_t)k * WPITCH + (uint32_t)(4 * lane + g) * 2;
            *reinterpret_cast<uint16_t*>(smem + OFF_W + o)         = hi;
            *reinterpret_cast<uint16_t*>(smem + OFF_W + WHALF + o) = lo;
        }
    }
    // zero h panel buffer 0 (both halves)
    for (int i = tid; i < AHBUF / 4; i += NTHREADS)
        reinterpret_cast<uint32_t*>(smem + OFF_AH)[i] = 0;

    // ---- lane offsets for ldmatrix.x4.trans ----
    const int lg = lane >> 3, lr = lane & 7;
    const uint32_t aoff = (uint32_t)((((lg & 2) ? 8 : 0) + lr) * 32 + ((lg & 1) ? 16 : 0));
    const uint32_t boff = (uint32_t)((((lg & 1) ? 8 : 0) + lr) * WPITCH
                                     + (16 * warp + ((lg & 2) ? 8 : 0)) * 2);

    // ---- bias constants (per n-tile col pair; go into chain A init only) ----
    float biasA[2], biasB[2];
    #pragma unroll
    for (int j = 0; j < 2; ++j) {
        int c0 = 16 * warp + 8 * j + 2 * (lane & 3);
        int hd0 = c0 >> 2, g0 = c0 & 3;
        const float* p0 = (g0 == 0) ? b_i : (g0 == 2) ? b_c : (g0 == 1) ? b_f : b_o;
        const float* p1 = (g0 + 1 == 1) ? b_f : (g0 + 1 == 3) ? b_o : (g0 + 1 == 2) ? b_c : b_i;
        biasA[j] = p0[colh + hd0];
        biasB[j] = p1[colh + hd0];
    }

    // ---- epilogue (fragment-layout) constants ----
    const int odd  = lane & 1;
    const int ebat = (lane >> 2) + (odd ? 8 : 0);            // owned batch (both j)
    const int hdj0 = 4 * warp + ((lane & 3) >> 1);           // hd for j=0; j=1 adds 2
    const int ghd0 = colh + hdj0;

    // ---- pusher constants (tid < 128): 16-B chunk (hd, half, bgroup) ----
    const int phd   = tid & 31;
    const int phalf = (tid >> 5) & 1;
    const int pbg   = (tid >> 6) & 1;
    const uint32_t psrc  = (uint32_t)(phd * 64 + phalf * 32 + pbg * 16);
    const uint32_t pdoff = (uint32_t)(phalf * 8192 + (colh + phd) * 32 + pbg * 16);
    uint32_t mbAH[CLUSTER], mbMB[CLUSTER];
    #pragma unroll
    for (int p = 0; p < CLUSTER; ++p) {
        mbAH[p] = mapa_u32(sb + OFF_AH, (uint32_t)p);
        mbMB[p] = mapa_u32(mbar, (uint32_t)p);
    }

    // ---- x staging: thread (bx, kg) handles x[gb+bx][t][4kg..4kg+3] ----
    const int bx = tid & 15;
    const int kg = tid >> 4;
    const float* xsrc = x + (size_t)(gb + bx) * S_DIM * I_DIM + 4 * kg;

    {
        float4 v = *reinterpret_cast<const float4*>(xsrc);
        float vv[4] = {v.x, v.y, v.z, v.w};
        #pragma unroll
        for (int j = 0; j < 4; ++j) {
            uint16_t hi, lo;
            bfsplit(vv[j], hi, lo);
            uint32_t o = (uint32_t)(4 * kg + j) * 32 + (uint32_t)bx * 2;
            *reinterpret_cast<uint16_t*>(smem + OFF_AX + o)        = hi;
            *reinterpret_cast<uint16_t*>(smem + OFF_AX + 2048 + o) = lo;
        }
    }
    float4 xv = *reinterpret_cast<const float4*>(xsrc + I_DIM);  // x_1 prefetch

    __syncthreads();   // weights staged + mbar init done (locally)

    // ---- hoist ALL B (weight) fragments into registers: 20 ks x 4 x 2 halves ----
    uint32_t wbh[20][4], wbl[20][4];
    {
        const uint32_t wb = sb + OFF_W + boff;
        #pragma unroll
        for (int ks = 0; ks < 20; ++ks) {
            LDSM4T(wbh[ks][0], wbh[ks][1], wbh[ks][2], wbh[ks][3],
                   wb + (uint32_t)ks * (16 * WPITCH));
            LDSM4T(wbl[ks][0], wbl[ks][1], wbl[ks][2], wbl[ks][3],
                   wb + (uint32_t)ks * (16 * WPITCH) + WHALF);
        }
    }

    // one-time full cluster sync: publishes mbar init before any remote arrive
    CLUSTER_SYNC();
    // prime phase 0 (h buffer 0 locally zeroed; no peer data needed at t=0)
    if (tid == 0) MBAR_ARRIVE_LOCAL_CNT(mbar, 8);

    float cs[2] = {0.f, 0.f};
    float hv[2] = {0.f, 0.f};

    for (int t = 0; t < S_DIM; ++t) {
        const int cur = t & 1;
        const int nxt = cur ^ 1;

        float aA[2][4], aB[2][4], aC[2][4];
        #pragma unroll
        for (int j = 0; j < 2; ++j) {
            aA[j][0] = biasA[j]; aA[j][1] = biasB[j];
            aA[j][2] = biasA[j]; aA[j][3] = biasB[j];
            aB[j][0] = 0.f; aB[j][1] = 0.f; aB[j][2] = 0.f; aB[j][3] = 0.f;
            aC[j][0] = 0.f; aC[j][1] = 0.f; aC[j][2] = 0.f; aC[j][3] = 0.f;
        }

        const uint32_t axb = sb + OFF_AX + (uint32_t)cur * AXBUF + aoff;
        const uint32_t ahb = sb + OFF_AH + (uint32_t)cur * AHBUF + aoff;

        uint32_t fah[2][4], fal[2][4];

        // ===== phase 1: x-part (4 ks) — independent of peers' h, overlaps join =====
        LOADA(0, axb, 2048u);
        #pragma unroll
        for (int ks = 0; ks < 4; ++ks) {
            const int s = ks & 1, n = s ^ 1;
            if (ks + 1 < 4)
                LOADA(n, axb + (uint32_t)(ks + 1) * 512, 2048u);
            MMA6S(fah[s], fal[s], wbh[ks], wbl[ks]);
        }

        // ===== join: peers' h pushes for buf cur visible (acquire.cluster) =====
        MBAR_WAIT_CLUSTER(mbar, (uint32_t)(t & 1));

        // ===== phase 2: h-part (16 ks), register double-buffered A =====
        LOADA(0, ahb, 8192u);
        #pragma unroll
        for (int ks = 0; ks < 16; ++ks) {
            const int s = ks & 1, n = s ^ 1;
            if (ks + 1 < 16)
                LOADA(n, ahb + (uint32_t)(ks + 1) * 512, 8192u);
            MMA6S(fah[s], fal[s], wbh[4 + ks], wbl[4 + ks]);
        }

        // ---- stage x_{t+1} into buf nxt; prefetch x_{t+2} ----
        if (t + 1 < S_DIM) {
            const uint32_t xo = OFF_AX + (uint32_t)nxt * AXBUF;
            float vv[4] = {xv.x, xv.y, xv.z, xv.w};
            #pragma unroll
            for (int j = 0; j < 4; ++j) {
                uint16_t hi, lo;
                bfsplit(vv[j], hi, lo);
                uint32_t o = (uint32_t)(4 * kg + j) * 32 + (uint32_t)bx * 2;
                *reinterpret_cast<uint16_t*>(smem + xo + o)        = hi;
                *reinterpret_cast<uint16_t*>(smem + xo + 2048 + o) = lo;
            }
            if (t + 2 < S_DIM)
                xv = *reinterpret_cast<const float4*>(xsrc + (size_t)(t + 2) * I_DIM);
        }

        // ---- fragment-layout epilogue: shfl-exchange gates ----
        const uint32_t bo = (uint32_t)nxt * AHBUF;
        #pragma unroll
        for (int j = 0; j < 2; ++j) {
            float e0 = aA[j][0] + aB[j][0] + aC[j][0];
            float e1 = aA[j][1] + aB[j][1] + aC[j][1];
            float e2 = aA[j][2] + aB[j][2] + aC[j][2];
            float e3 = aA[j][3] + aB[j][3] + aC[j][3];

            float s1 = odd ? e0 : e2;
            float s2 = odd ? e1 : e3;
            float r1 = __shfl_xor_sync(0xffffffffu, s1, 1);
            float r2 = __shfl_xor_sync(0xffffffffu, s2, 1);
            float gi = odd ? r1 : e0;
            float gf = odd ? r2 : e1;
            float gg = odd ? e2 : r1;
            float go = odd ? e3 : r2;

            float it = sigf(gi), ft = sigf(gf), gt = tanh_(gg), ot = sigf(go);
            cs[j] = fmaf(ft, cs[j], it * gt);
            hv[j] = ot * tanh_(cs[j]);

            const int ghd = ghd0 + 2 * j;
            out[(size_t)t * (B_DIM * H_DIM) + (size_t)(gb + ebat) * H_DIM + ghd] = hv[j];

            uint16_t hh, hl;
            bfsplit(hv[j], hh, hl);
            *reinterpret_cast<uint16_t*>(smem + OFF_AH + bo + (uint32_t)(ghd * 32 + ebat * 2))        = hh;
            *reinterpret_cast<uint16_t*>(smem + OFF_AH + bo + 8192 + (uint32_t)(ghd * 32 + ebat * 2)) = hl;
            const int hdl = hdj0 + 2 * j;
            *reinterpret_cast<uint16_t*>(smem + OFF_HSTG + (uint32_t)(hdl * 64 + ebat * 2))      = hh;
            *reinterpret_cast<uint16_t*>(smem + OFF_HSTG + (uint32_t)(hdl * 64 + 32 + ebat * 2)) = hl;
        }

        __syncthreads();   // Hstg + own slice + x staging complete

        // ---- compact push + mbarrier join arrive ----
        if (t + 1 < S_DIM) {
            if (tid < 128) {
                uint4 v = *reinterpret_cast<const uint4*>(smem + OFF_HSTG + psrc);
                #pragma unroll
                for (int p = 0; p < CLUSTER; ++p)
                    if ((uint32_t)p != rank)
                        stc128(mbAH[p] + bo + pdoff, v);
                // pushers sync, then one thread releases to all 8 mbarriers
                asm volatile("bar.sync 1, 128;" ::: "memory");
                if (tid == 0) {
                    #pragma unroll
                    for (int p = 0; p < CLUSTER; ++p)
                        MBAR_ARRIVE_REMOTE(mbMB[p]);
                }
            }
        }
    }

    // ---- final h_t, c_t ----
    float* out_h = out + (size_t)S_DIM * B_DIM * H_DIM;
    float* out_c = out_h + (size_t)B_DIM * H_DIM;
    #pragma unroll
    for (int j = 0; j < 2; ++j) {
        const size_t fb = (size_t)(gb + ebat) * H_DIM + (ghd0 + 2 * j);
        out_h[fb] = hv[j];
        out_c[fb] = cs[j];
    }

    // keep cluster resident until all CTAs are done with remote traffic
    CLUSTER_SYNC();
}

extern "C" void kernel_launch(void* const* d_in, const int* in_sizes, int n_in,
                              void* d_out, int out_size) {
    const float* x   = (const float*)d_in[0];
    const float* w_i = (const float*)d_in[1];
    const float* u_i = (const float*)d_in[2];
    const float* b_i = (const float*)d_in[3];
    const float* w_f = (const float*)d_in[4];
    const float* u_f = (const float*)d_in[5];
    const float* b_f = (const float*)d_in[6];
    const float* w_c = (const float*)d_in[7];
    const float* u_c = (const float*)d_in[8];
    const float* b_c = (const float*)d_in[9];
    const float* w_o = (const float*)d_in[10];
    const float* u_o = (const float*)d_in[11];
    const float* b_o = (const float*)d_in[12];
    float* out = (float*)d_out;

    cudaFuncSetAttribute(lstm_hmma, cudaFuncAttributeMaxDynamicSharedMemorySize, SMEM_BYTES);

    dim3 grid((B_DIM / GBATCH) * CLUSTER);  // 16 clusters * 8 CTAs = 128
    lstm_hmma<<<grid, NTHREADS, SMEM_BYTES>>>(
        x, w_i, u_i, b_i, w_f, u_f, b_f, w_c, u_c, b_c, w_o, u_o, b_o, out);
}

// round 13
// speedup vs baseline: 1.1981x; 1.1981x over previous
#include <cuda_runtime.h>
#include <cuda_bf16.h>
#include <cstdint>

// Problem dims
#define B_DIM 256
#define S_DIM 512
#define I_DIM 64
#define H_DIM 256

#define CLUSTER 8
#define GBATCH 16
#define HSLICE 32
#define NTHREADS 256      // 8 warps

#define WPITCH 272

// ===== recurrent kernel smem: U weights only (k = 64..319 -> rows 0..255) =====
#define OFF_W   0
#define WHALF   (256 * WPITCH)            // 69632
#define OFF_AH  (2 * WHALF)               // 139264: [2 buf][2 half][256 k][16 b]
#define AHBUF   16384
#define OFF_HSTG (OFF_AH + 2 * AHBUF)     // 172032: [32 hd][2 half][16 b] = 2KB
#define SMEM_BYTES (OFF_HSTG + 2048)      // 174080

// ===== pre-pass smem: W x-slice + x panels =====
#define PRE_WHALF (64 * WPITCH)           // 17408
#define PRE_OFF_AX (2 * PRE_WHALF)        // 34816
#define PRE_AXBUF 4096
#define PRE_SMEM (PRE_OFF_AX + 2 * PRE_AXBUF)  // 43008

// xq scratch: [512 t][128 cta][256 tid][8] fp32, fragment order
__device__ float g_xq[512ull * 128ull * 2048ull];

__device__ __forceinline__ float sigf(float x) {
    return __fdividef(1.0f, 1.0f + __expf(-x));
}
__device__ __forceinline__ float tanh_(float x) {
    return __fdividef(2.0f, 1.0f + __expf(-2.0f * x)) - 1.0f;
}

__device__ __forceinline__ uint32_t smem_u32(const void* p) {
    uint32_t a;
    asm("{ .reg .u64 t; cvta.to.shared.u64 t, %1; cvt.u32.u64 %0, t; }" : "=r"(a) : "l"(p));
    return a;
}
__device__ __forceinline__ uint32_t mapa_u32(uint32_t addr, uint32_t rank) {
    uint32_t r;
    asm("mapa.shared::cluster.u32 %0, %1, %2;" : "=r"(r) : "r"(addr), "r"(rank));
    return r;
}
__device__ __forceinline__ void stc128(uint32_t addr, uint4 v) {
    asm volatile("st.shared::cluster.v4.b32 [%0], {%1,%2,%3,%4};"
                 :: "r"(addr), "r"(v.x), "r"(v.y), "r"(v.z), "r"(v.w) : "memory");
}
#define CLUSTER_ARRIVE() asm volatile("barrier.cluster.arrive.aligned;" ::: "memory")
#define CLUSTER_WAIT()   asm volatile("barrier.cluster.wait.aligned;" ::: "memory")

#define LDSM4T(r0, r1, r2, r3, addr) \
    asm volatile("ldmatrix.sync.aligned.m8n8.x4.trans.shared.b16 {%0,%1,%2,%3}, [%4];" \
                 : "=r"(r0), "=r"(r1), "=r"(r2), "=r"(r3) : "r"(addr))

#define MMA(d0, d1, d2, d3, a0, a1, a2, a3, b0, b1) \
    asm volatile("mma.sync.aligned.m16n8k16.row.col.f32.bf16.bf16.f32 " \
                 "{%0,%1,%2,%3}, {%4,%5,%6,%7}, {%8,%9}, {%0,%1,%2,%3};" \
                 : "+f"(d0), "+f"(d1), "+f"(d2), "+f"(d3) \
                 : "r"(a0), "r"(a1), "r"(a2), "r"(a3), "r"(b0), "r"(b1))

__device__ __forceinline__ void bfsplit(float v, uint16_t& hi, uint16_t& lo) {
    __nv_bfloat16 h = __float2bfloat16(v);
    float r = v - __bfloat162float(h);
    __nv_bfloat16 l = __float2bfloat16(r);
    hi = *reinterpret_cast<uint16_t*>(&h);
    lo = *reinterpret_cast<uint16_t*>(&l);
}

// 6 MMAs per k-step, 3 INDEPENDENT accumulator chains x 2 n-tiles
#define MMA6S(AH, AL, BH, BL) do { \
    MMA(aA[0][0], aA[0][1], aA[0][2], aA[0][3], (AH)[0], (AH)[1], (AH)[2], (AH)[3], (BH)[0], (BH)[1]); \
    MMA(aB[0][0], aB[0][1], aB[0][2], aB[0][3], (AH)[0], (AH)[1], (AH)[2], (AH)[3], (BL)[0], (BL)[1]); \
    MMA(aC[0][0], aC[0][1], aC[0][2], aC[0][3], (AL)[0], (AL)[1], (AL)[2], (AL)[3], (BH)[0], (BH)[1]); \
    MMA(aA[1][0], aA[1][1], aA[1][2], aA[1][3], (AH)[0], (AH)[1], (AH)[2], (AH)[3], (BH)[2], (BH)[3]); \
    MMA(aB[1][0], aB[1][1], aB[1][2], aB[1][3], (AH)[0], (AH)[1], (AH)[2], (AH)[3], (BL)[2], (BL)[3]); \
    MMA(aC[1][0], aC[1][1], aC[1][2], aC[1][3], (AL)[0], (AL)[1], (AL)[2], (AL)[3], (BH)[2], (BH)[3]); \
} while (0)

// A-only k-step load (hi + lo halves)
#define LOADA(S, AADDR, ALOFF) do { \
    LDSM4T(fah[S][0], fah[S][1], fah[S][2], fah[S][3], (AADDR)); \
    LDSM4T(fal[S][0], fal[S][1], fal[S][2], fal[S][3], (AADDR) + (ALOFF)); \
} while (0)

// ===================== pre-pass: xq[t] = x_t @ W + b, fragment order =====================
__global__ void __launch_bounds__(NTHREADS, 1)
lstm_prepass(const float* __restrict__ x,
             const float* __restrict__ w_i, const float* __restrict__ b_i,
             const float* __restrict__ w_f, const float* __restrict__ b_f,
             const float* __restrict__ w_c, const float* __restrict__ b_c,
             const float* __restrict__ w_o, const float* __restrict__ b_o)
{
    extern __shared__ char smem[];
    const uint32_t sb = smem_u32(smem);
    const int tid  = threadIdx.x;
    const int lane = tid & 31;
    const int warp = tid >> 5;

    const int cta  = blockIdx.x;          // 0..127, matches recurrent CTA id
    const int rank = cta & 7;
    const int gb   = (cta >> 3) * GBATCH;
    const int colh = rank * HSLICE;

    // stage W x-slice (k < 64), gate-interleaved cols, bf16 hi/lo
    #pragma unroll
    for (int g = 0; g < 4; ++g) {
        const float* Wsrc = (g == 0) ? w_i : (g == 1) ? w_f : (g == 2) ? w_c : w_o;
        for (int k = warp; k < I_DIM; k += 8) {
            float v = Wsrc[(size_t)k * H_DIM + colh + lane];
            uint16_t hi, lo;
            bfsplit(v, hi, lo);
            uint32_t o = (uint32_t)k * WPITCH + (uint32_t)(4 * lane + g) * 2;
            *reinterpret_cast<uint16_t*>(smem + o)             = hi;
            *reinterpret_cast<uint16_t*>(smem + PRE_WHALF + o) = lo;
        }
    }

    const int lg = lane >> 3, lr = lane & 7;
    const uint32_t aoff = (uint32_t)((((lg & 2) ? 8 : 0) + lr) * 32 + ((lg & 1) ? 16 : 0));
    const uint32_t boff = (uint32_t)((((lg & 1) ? 8 : 0) + lr) * WPITCH
                                     + (16 * warp + ((lg & 2) ? 8 : 0)) * 2);

    float biasA[2], biasB[2];
    #pragma unroll
    for (int j = 0; j < 2; ++j) {
        int c0 = 16 * warp + 8 * j + 2 * (lane & 3);
        int hd0 = c0 >> 2, g0 = c0 & 3;
        const float* p0 = (g0 == 0) ? b_i : (g0 == 2) ? b_c : (g0 == 1) ? b_f : b_o;
        const float* p1 = (g0 + 1 == 1) ? b_f : (g0 + 1 == 3) ? b_o : (g0 + 1 == 2) ? b_c : b_i;
        biasA[j] = p0[colh + hd0];
        biasB[j] = p1[colh + hd0];
    }

    // x staging: thread (bx, kg) handles x[gb+bx][t][4kg..4kg+3]
    const int bx = tid & 15;
    const int kg = tid >> 4;
    const int t0 = blockIdx.y * 32;
    const float* xsrc = x + (size_t)(gb + bx) * S_DIM * I_DIM + 4 * kg;

    // stage x(t0) into buf 0
    {
        float4 v = *reinterpret_cast<const float4*>(xsrc + (size_t)t0 * I_DIM);
        float vv[4] = {v.x, v.y, v.z, v.w};
        #pragma unroll
        for (int j = 0; j < 4; ++j) {
            uint16_t hi, lo;
            bfsplit(vv[j], hi, lo);
            uint32_t o = (uint32_t)(4 * kg + j) * 32 + (uint32_t)bx * 2;
            *reinterpret_cast<uint16_t*>(smem + PRE_OFF_AX + o)        = hi;
            *reinterpret_cast<uint16_t*>(smem + PRE_OFF_AX + 2048 + o) = lo;
        }
    }
    float4 xv = *reinterpret_cast<const float4*>(xsrc + (size_t)(t0 + 1) * I_DIM);
    __syncthreads();

    // hoist B fragments for the 4 x-k-steps
    uint32_t wbh4[4][4], wbl4[4][4];
    {
        const uint32_t wb = sb + boff;
        #pragma unroll
        for (int ks = 0; ks < 4; ++ks) {
            LDSM4T(wbh4[ks][0], wbh4[ks][1], wbh4[ks][2], wbh4[ks][3],
                   wb + (uint32_t)ks * (16 * WPITCH));
            LDSM4T(wbl4[ks][0], wbl4[ks][1], wbl4[ks][2], wbl4[ks][3],
                   wb + (uint32_t)ks * (16 * WPITCH) + PRE_WHALF);
        }
    }

    for (int i = 0; i < 32; ++i) {
        const int t = t0 + i;
        const int cur = i & 1, nxt = cur ^ 1;

        float aA[2][4], aB[2][4], aC[2][4];
        #pragma unroll
        for (int j = 0; j < 2; ++j) {
            aA[j][0] = biasA[j]; aA[j][1] = biasB[j];
            aA[j][2] = biasA[j]; aA[j][3] = biasB[j];
            aB[j][0] = 0.f; aB[j][1] = 0.f; aB[j][2] = 0.f; aB[j][3] = 0.f;
            aC[j][0] = 0.f; aC[j][1] = 0.f; aC[j][2] = 0.f; aC[j][3] = 0.f;
        }

        const uint32_t axb = sb + PRE_OFF_AX + (uint32_t)cur * PRE_AXBUF + aoff;
        uint32_t fah[2][4], fal[2][4];
        LOADA(0, axb, 2048u);
        #pragma unroll
        for (int ks = 0; ks < 4; ++ks) {
            const int s = ks & 1, n = s ^ 1;
            if (ks + 1 < 4)
                LOADA(n, axb + (uint32_t)(ks + 1) * 512, 2048u);
            MMA6S(fah[s], fal[s], wbh4[ks], wbl4[ks]);
        }

        // stage x(t+1) into nxt; prefetch x(t+2)
        if (t + 1 < S_DIM) {
            float vv[4] = {xv.x, xv.y, xv.z, xv.w};
            #pragma unroll
            for (int j = 0; j < 4; ++j) {
                uint16_t hi, lo;
                bfsplit(vv[j], hi, lo);
                uint32_t o = (uint32_t)(4 * kg + j) * 32 + (uint32_t)bx * 2;
                *reinterpret_cast<uint16_t*>(smem + PRE_OFF_AX + (uint32_t)nxt * PRE_AXBUF + o)        = hi;
                *reinterpret_cast<uint16_t*>(smem + PRE_OFF_AX + (uint32_t)nxt * PRE_AXBUF + 2048 + o) = lo;
            }
            if (t + 2 < S_DIM)
                xv = *reinterpret_cast<const float4*>(xsrc + (size_t)(t + 2) * I_DIM);
        }

        // store fragment-order xq
        float4 v0 = make_float4(aA[0][0] + aB[0][0] + aC[0][0],
                                aA[0][1] + aB[0][1] + aC[0][1],
                                aA[0][2] + aB[0][2] + aC[0][2],
                                aA[0][3] + aB[0][3] + aC[0][3]);
        float4 v1 = make_float4(aA[1][0] + aB[1][0] + aC[1][0],
                                aA[1][1] + aB[1][1] + aC[1][1],
                                aA[1][2] + aB[1][2] + aC[1][2],
                                aA[1][3] + aB[1][3] + aC[1][3]);
        size_t base = ((size_t)t * 128 + (size_t)cta) * 2048 + (size_t)tid * 8;
        *reinterpret_cast<float4*>(&g_xq[base])     = v0;
        *reinterpret_cast<float4*>(&g_xq[base + 4]) = v1;

        __syncthreads();   // next iter's MMA may read buf nxt
    }
}

// ===================== recurrent kernel =====================
__global__ void __cluster_dims__(CLUSTER, 1, 1) __launch_bounds__(NTHREADS, 1)
lstm_hmma(const float* __restrict__ u_i, const float* __restrict__ u_f,
          const float* __restrict__ u_c, const float* __restrict__ u_o,
          float* __restrict__ out)
{
    extern __shared__ char smem[];
    const uint32_t sb = smem_u32(smem);
    const int tid  = threadIdx.x;
    const int lane = tid & 31;
    const int warp = tid >> 5;

    uint32_t rank;
    asm("mov.u32 %0, %%cluster_ctarank;" : "=r"(rank));
    const int gb   = (blockIdx.x / CLUSTER) * GBATCH;
    const int colh = (int)rank * HSLICE;

    // ---- stage U weights (k2 = 0..255 <-> original k = 64..319) ----
    #pragma unroll
    for (int g = 0; g < 4; ++g) {
        const float* Usrc = (g == 0) ? u_i : (g == 1) ? u_f : (g == 2) ? u_c : u_o;
        for (int k2 = warp; k2 < 256; k2 += 8) {
            float v = Usrc[(size_t)k2 * H_DIM + colh + lane];
            uint16_t hi, lo;
            bfsplit(v, hi, lo);
            uint32_t o = (uint32_t)k2 * WPITCH + (uint32_t)(4 * lane + g) * 2;
            *reinterpret_cast<uint16_t*>(smem + OFF_W + o)         = hi;
            *reinterpret_cast<uint16_t*>(smem + OFF_W + WHALF + o) = lo;
        }
    }
    // zero h panel buffer 0 (both halves)
    for (int i = tid; i < AHBUF / 4; i += NTHREADS)
        reinterpret_cast<uint32_t*>(smem + OFF_AH)[i] = 0;

    // ---- lane offsets ----
    const int lg = lane >> 3, lr = lane & 7;
    const uint32_t aoff = (uint32_t)((((lg & 2) ? 8 : 0) + lr) * 32 + ((lg & 1) ? 16 : 0));
    const uint32_t boff = (uint32_t)((((lg & 1) ? 8 : 0) + lr) * WPITCH
                                     + (16 * warp + ((lg & 2) ? 8 : 0)) * 2);

    // ---- epilogue constants ----
    const int odd  = lane & 1;
    const int ebat = (lane >> 2) + (odd ? 8 : 0);
    const int hdj0 = 4 * warp + ((lane & 3) >> 1);
    const int ghd0 = colh + hdj0;

    // ---- pusher constants (tid < 128) ----
    const int phd   = tid & 31;
    const int phalf = (tid >> 5) & 1;
    const int pbg   = (tid >> 6) & 1;
    const uint32_t psrc  = (uint32_t)(phd * 64 + phalf * 32 + pbg * 16);
    const uint32_t pdoff = (uint32_t)(phalf * 8192 + (colh + phd) * 32 + pbg * 16);
    uint32_t mbAH[CLUSTER];
    #pragma unroll
    for (int p = 0; p < CLUSTER; ++p) mbAH[p] = mapa_u32(sb + OFF_AH, (uint32_t)p);

    __syncthreads();   // weights staged — safe to hoist B fragments

    // ---- hoist B fragments: 16 h-k-steps x 4 x 2 halves ----
    uint32_t wbh[16][4], wbl[16][4];
    {
        const uint32_t wb = sb + OFF_W + boff;
        #pragma unroll
        for (int ks = 0; ks < 16; ++ks) {
            LDSM4T(wbh[ks][0], wbh[ks][1], wbh[ks][2], wbh[ks][3],
                   wb + (uint32_t)ks * (16 * WPITCH));
            LDSM4T(wbl[ks][0], wbl[ks][1], wbl[ks][2], wbl[ks][3],
                   wb + (uint32_t)ks * (16 * WPITCH) + WHALF);
        }
    }

    // ---- xq pointer + preload t=0 ----
    const float* xqp = g_xq + (size_t)blockIdx.x * 2048 + (size_t)tid * 8;
    float4 q0 = *reinterpret_cast<const float4*>(xqp);
    float4 q1 = *reinterpret_cast<const float4*>(xqp + 4);

    float cs[2] = {0.f, 0.f};
    float hv[2] = {0.f, 0.f};

    CLUSTER_ARRIVE();   // primes iteration-0 wait (h buffer 0 locally zeroed)

    for (int t = 0; t < S_DIM; ++t) {
        const int cur = t & 1;
        const int nxt = cur ^ 1;

        // acc init = precomputed x-projection + bias (chain A); B/C zero
        float aA[2][4], aB[2][4], aC[2][4];
        aA[0][0] = q0.x; aA[0][1] = q0.y; aA[0][2] = q0.z; aA[0][3] = q0.w;
        aA[1][0] = q1.x; aA[1][1] = q1.y; aA[1][2] = q1.z; aA[1][3] = q1.w;
        #pragma unroll
        for (int j = 0; j < 2; ++j) {
            aB[j][0] = 0.f; aB[j][1] = 0.f; aB[j][2] = 0.f; aB[j][3] = 0.f;
            aC[j][0] = 0.f; aC[j][1] = 0.f; aC[j][2] = 0.f; aC[j][3] = 0.f;
        }

        // prefetch xq(t+1) — lands during the wait + h-phase
        if (t + 1 < S_DIM) {
            const float* np = xqp + (size_t)(t + 1) * (128 * 2048);
            q0 = *reinterpret_cast<const float4*>(np);
            q1 = *reinterpret_cast<const float4*>(np + 4);
        }

        // ===== join: peers' h pushes for buf cur visible =====
        CLUSTER_WAIT();

        // ===== h-part (16 ks), register double-buffered A =====
        const uint32_t ahb = sb + OFF_AH + (uint32_t)cur * AHBUF + aoff;
        uint32_t fah[2][4], fal[2][4];
        LOADA(0, ahb, 8192u);
        #pragma unroll
        for (int ks = 0; ks < 16; ++ks) {
            const int s = ks & 1, n = s ^ 1;
            if (ks + 1 < 16)
                LOADA(n, ahb + (uint32_t)(ks + 1) * 512, 8192u);
            MMA6S(fah[s], fal[s], wbh[ks], wbl[ks]);
        }

        // ---- fragment-layout epilogue: shfl-exchange gates ----
        const uint32_t bo = (uint32_t)nxt * AHBUF;
        #pragma unroll
        for (int j = 0; j < 2; ++j) {
            float e0 = aA[j][0] + aB[j][0] + aC[j][0];
            float e1 = aA[j][1] + aB[j][1] + aC[j][1];
            float e2 = aA[j][2] + aB[j][2] + aC[j][2];
            float e3 = aA[j][3] + aB[j][3] + aC[j][3];

            float s1 = odd ? e0 : e2;
            float s2 = odd ? e1 : e3;
            float r1 = __shfl_xor_sync(0xffffffffu, s1, 1);
            float r2 = __shfl_xor_sync(0xffffffffu, s2, 1);
            float gi = odd ? r1 : e0;
            float gf = odd ? r2 : e1;
            float gg = odd ? e2 : r1;
            float go = odd ? e3 : r2;

            float it = sigf(gi), ft = sigf(gf), gt = tanh_(gg), ot = sigf(go);
            cs[j] = fmaf(ft, cs[j], it * gt);
            hv[j] = ot * tanh_(cs[j]);

            const int ghd = ghd0 + 2 * j;
            uint16_t hh, hl;
            bfsplit(hv[j], hh, hl);
            // own panel slice (buf nxt)
            *reinterpret_cast<uint16_t*>(smem + OFF_AH + bo + (uint32_t)(ghd * 32 + ebat * 2))        = hh;
            *reinterpret_cast<uint16_t*>(smem + OFF_AH + bo + 8192 + (uint32_t)(ghd * 32 + ebat * 2)) = hl;
            // push staging [hd][half][b]
            const int hdl = hdj0 + 2 * j;
            *reinterpret_cast<uint16_t*>(smem + OFF_HSTG + (uint32_t)(hdl * 64 + ebat * 2))      = hh;
            *reinterpret_cast<uint16_t*>(smem + OFF_HSTG + (uint32_t)(hdl * 64 + 32 + ebat * 2)) = hl;
        }

        __syncthreads();   // Hstg + own slice complete

        // ---- compact push: 128 threads x 7 peers x 16B, then release ----
        if (t + 1 < S_DIM) {
            if (tid < 128) {
                uint4 v = *reinterpret_cast<const uint4*>(smem + OFF_HSTG + psrc);
                #pragma unroll
                for (int p = 0; p < CLUSTER; ++p)
                    if ((uint32_t)p != rank)
                        stc128(mbAH[p] + bo + pdoff, v);
            }
            CLUSTER_ARRIVE();
        }

        // hidden_seq stores AFTER the release — off the inter-CTA critical path
        float* op = out + (size_t)t * (B_DIM * H_DIM) + (size_t)(gb + ebat) * H_DIM + ghd0;
        op[0] = hv[0];
        op[2] = hv[1];
    }

    // ---- final h_t, c_t ----
    float* out_h = out + (size_t)S_DIM * B_DIM * H_DIM;
    float* out_c = out_h + (size_t)B_DIM * H_DIM;
    #pragma unroll
    for (int j = 0; j < 2; ++j) {
        const size_t fb = (size_t)(gb + ebat) * H_DIM + (ghd0 + 2 * j);
        out_h[fb] = hv[j];
        out_c[fb] = cs[j];
    }
}

extern "C" void kernel_launch(void* const* d_in, const int* in_sizes, int n_in,
                              void* d_out, int out_size) {
    const float* x   = (const float*)d_in[0];
    const float* w_i = (const float*)d_in[1];
    const float* u_i = (const float*)d_in[2];
    const float* b_i = (const float*)d_in[3];
    const float* w_f = (const float*)d_in[4];
    const float* u_f = (const float*)d_in[5];
    const float* b_f = (const float*)d_in[6];
    const float* w_c = (const float*)d_in[7];
    const float* u_c = (const float*)d_in[8];
    const float* b_c = (const float*)d_in[9];
    const float* w_o = (const float*)d_in[10];
    const float* u_o = (const float*)d_in[11];
    const float* b_o = (const float*)d_in[12];
    float* out = (float*)d_out;

    cudaFuncSetAttribute(lstm_prepass, cudaFuncAttributeMaxDynamicSharedMemorySize, PRE_SMEM);
    cudaFuncSetAttribute(lstm_hmma,    cudaFuncAttributeMaxDynamicSharedMemorySize, SMEM_BYTES);

    // pre-pass: xq[t][cta][fragment] = x_t @ W + b
    lstm_prepass<<<dim3(128, 16), NTHREADS, PRE_SMEM>>>(
        x, w_i, b_i, w_f, b_f, w_c, b_c, w_o, b_o);

    // recurrent kernel: 16 clusters x 8 CTAs
    lstm_hmma<<<dim3((B_DIM / GBATCH) * CLUSTER), NTHREADS, SMEM_BYTES>>>(
        u_i, u_f, u_c, u_o, out);
}

// round 14
// speedup vs baseline: 1.3604x; 1.1354x over previous
#include <cuda_runtime.h>
#include <cuda_bf16.h>
#include <cstdint>

// Problem dims
#define B_DIM 256
#define S_DIM 512
#define I_DIM 64
#define H_DIM 256

#define CLUSTER 8
#define GBATCH 16
#define HSLICE 32
#define NTHREADS 256      // 8 warps

// Weights: [2 half][320 k][128 n] bf16, pitch 272B (conflict-free LDSM)
// h rows (k=64..319) are stored ROTATED per CTA: U dim d at row 64 + ((d - 32*rank) & 255)
#define WPITCH 272
#define OFF_W   0
#define WHALF   (320 * WPITCH)            // 87040
// A x-panel: [2 buf][2 half][64 k][16 b] bf16
#define OFF_AX  (2 * WHALF)               // 174080
#define AXBUF   4096
// A h-panel: [2 buf][2 half][256 k][16 b] bf16, rows rotated identically to U
#define OFF_AH  (OFF_AX + 2 * AXBUF)      // 182272
#define AHBUF   16384
// h staging for compact pushes: [32 hd][2 half][16 b] bf16 = 2KB (local dim order)
#define OFF_HSTG (OFF_AH + 2 * AHBUF)     // 215040
#define SMEM_BYTES (OFF_HSTG + 2048)      // 217088

__device__ __forceinline__ float sigf(float x) {
    return __fdividef(1.0f, 1.0f + __expf(-x));
}
__device__ __forceinline__ float tanh_(float x) {
    return __fdividef(2.0f, 1.0f + __expf(-2.0f * x)) - 1.0f;
}

__device__ __forceinline__ uint32_t smem_u32(const void* p) {
    uint32_t a;
    asm("{ .reg .u64 t; cvta.to.shared.u64 t, %1; cvt.u32.u64 %0, t; }" : "=r"(a) : "l"(p));
    return a;
}
__device__ __forceinline__ uint32_t mapa_u32(uint32_t addr, uint32_t rank) {
    uint32_t r;
    asm("mapa.shared::cluster.u32 %0, %1, %2;" : "=r"(r) : "r"(addr), "r"(rank));
    return r;
}
__device__ __forceinline__ void stc128(uint32_t addr, uint4 v) {
    asm volatile("st.shared::cluster.v4.b32 [%0], {%1,%2,%3,%4};"
                 :: "r"(addr), "r"(v.x), "r"(v.y), "r"(v.z), "r"(v.w) : "memory");
}
#define CLUSTER_ARRIVE() asm volatile("barrier.cluster.arrive.aligned;" ::: "memory")
#define CLUSTER_WAIT()   asm volatile("barrier.cluster.wait.aligned;" ::: "memory")

#define LDSM4T(r0, r1, r2, r3, addr) \
    asm volatile("ldmatrix.sync.aligned.m8n8.x4.trans.shared.b16 {%0,%1,%2,%3}, [%4];" \
                 : "=r"(r0), "=r"(r1), "=r"(r2), "=r"(r3) : "r"(addr))

#define MMA(d0, d1, d2, d3, a0, a1, a2, a3, b0, b1) \
    asm volatile("mma.sync.aligned.m16n8k16.row.col.f32.bf16.bf16.f32 " \
                 "{%0,%1,%2,%3}, {%4,%5,%6,%7}, {%8,%9}, {%0,%1,%2,%3};" \
                 : "+f"(d0), "+f"(d1), "+f"(d2), "+f"(d3) \
                 : "r"(a0), "r"(a1), "r"(a2), "r"(a3), "r"(b0), "r"(b1))

__device__ __forceinline__ void bfsplit(float v, uint16_t& hi, uint16_t& lo) {
    __nv_bfloat16 h = __float2bfloat16(v);
    float r = v - __bfloat162float(h);
    __nv_bfloat16 l = __float2bfloat16(r);
    hi = *reinterpret_cast<uint16_t*>(&h);
    lo = *reinterpret_cast<uint16_t*>(&l);
}

// 6 MMAs per k-step, 3 INDEPENDENT accumulator chains x 2 n-tiles
#define MMA6S(AH, AL, BH, BL) do { \
    MMA(aA[0][0], aA[0][1], aA[0][2], aA[0][3], (AH)[0], (AH)[1], (AH)[2], (AH)[3], (BH)[0], (BH)[1]); \
    MMA(aB[0][0], aB[0][1], aB[0][2], aB[0][3], (AH)[0], (AH)[1], (AH)[2], (AH)[3], (BL)[0], (BL)[1]); \
    MMA(aC[0][0], aC[0][1], aC[0][2], aC[0][3], (AL)[0], (AL)[1], (AL)[2], (AL)[3], (BH)[0], (BH)[1]); \
    MMA(aA[1][0], aA[1][1], aA[1][2], aA[1][3], (AH)[0], (AH)[1], (AH)[2], (AH)[3], (BH)[2], (BH)[3]); \
    MMA(aB[1][0], aB[1][1], aB[1][2], aB[1][3], (AH)[0], (AH)[1], (AH)[2], (AH)[3], (BL)[2], (BL)[3]); \
    MMA(aC[1][0], aC[1][1], aC[1][2], aC[1][3], (AL)[0], (AL)[1], (AL)[2], (AL)[3], (BH)[2], (BH)[3]); \
} while (0)

// A-only k-step load (hi + lo halves); ALOFF = 2048 (x panel) or 8192 (h panel)
#define LOADA(S, AADDR, ALOFF) do { \
    LDSM4T(fah[S][0], fah[S][1], fah[S][2], fah[S][3], (AADDR)); \
    LDSM4T(fal[S][0], fal[S][1], fal[S][2], fal[S][3], (AADDR) + (ALOFF)); \
} while (0)

__global__ void __cluster_dims__(CLUSTER, 1, 1) __launch_bounds__(NTHREADS, 1)
lstm_hmma(const float* __restrict__ x,
          const float* __restrict__ w_i, const float* __restrict__ u_i, const float* __restrict__ b_i,
          const float* __restrict__ w_f, const float* __restrict__ u_f, const float* __restrict__ b_f,
          const float* __restrict__ w_c, const float* __restrict__ u_c, const float* __restrict__ b_c,
          const float* __restrict__ w_o, const float* __restrict__ u_o, const float* __restrict__ b_o,
          float* __restrict__ out)
{
    extern __shared__ char smem[];
    const uint32_t sb = smem_u32(smem);
    const int tid  = threadIdx.x;
    const int lane = tid & 31;
    const int warp = tid >> 5;

    uint32_t rank;
    asm("mov.u32 %0, %%cluster_ctarank;" : "=r"(rank));
    const int gb   = (blockIdx.x / CLUSTER) * GBATCH;
    const int colh = (int)rank * HSLICE;

    // ---- stage weights: x rows (k<64) unrotated, U rows rotated by 32*rank ----
    #pragma unroll
    for (int g = 0; g < 4; ++g) {
        const float* Wsrc = (g == 0) ? w_i : (g == 1) ? w_f : (g == 2) ? w_c : w_o;
        const float* Usrc = (g == 0) ? u_i : (g == 1) ? u_f : (g == 2) ? u_c : u_o;
        for (int k = warp; k < 320; k += 8) {
            const float* src;
            int row;
            if (k < I_DIM) { src = Wsrc + (size_t)k * H_DIM; row = k; }
            else {
                int d = k - I_DIM;
                src = Usrc + (size_t)d * H_DIM;
                row = I_DIM + ((d + 256 - 32 * (int)rank) & 255);
            }
            float v = src[colh + lane];
            uint16_t hi, lo;
            bfsplit(v, hi, lo);
            uint32_t o = (uint32_t)row * WPITCH + (uint32_t)(4 * lane + g) * 2;
            *reinterpret_cast<uint16_t*>(smem + OFF_W + o)         = hi;
            *reinterpret_cast<uint16_t*>(smem + OFF_W + WHALF + o) = lo;
        }
    }
    // zero h panel buffer 0 (both halves)
    for (int i = tid; i < AHBUF / 4; i += NTHREADS)
        reinterpret_cast<uint32_t*>(smem + OFF_AH)[i] = 0;

    // ---- lane offsets for ldmatrix.x4.trans ----
    const int lg = lane >> 3, lr = lane & 7;
    const uint32_t aoff = (uint32_t)((((lg & 2) ? 8 : 0) + lr) * 32 + ((lg & 1) ? 16 : 0));
    const uint32_t boff = (uint32_t)((((lg & 1) ? 8 : 0) + lr) * WPITCH
                                     + (16 * warp + ((lg & 2) ? 8 : 0)) * 2);

    // ---- bias constants (per n-tile col pair; chain A init only) ----
    float biasA[2], biasB[2];
    #pragma unroll
    for (int j = 0; j < 2; ++j) {
        int c0 = 16 * warp + 8 * j + 2 * (lane & 3);
        int hd0 = c0 >> 2, g0 = c0 & 3;
        const float* p0 = (g0 == 0) ? b_i : (g0 == 2) ? b_c : (g0 == 1) ? b_f : b_o;
        const float* p1 = (g0 + 1 == 1) ? b_f : (g0 + 1 == 3) ? b_o : (g0 + 1 == 2) ? b_c : b_i;
        biasA[j] = p0[colh + hd0];
        biasB[j] = p1[colh + hd0];
    }

    // ---- epilogue (fragment-layout) constants ----
    const int odd  = lane & 1;
    const int ebat = (lane >> 2) + (odd ? 8 : 0);            // owned batch (both j)
    const int hdj0 = 4 * warp + ((lane & 3) >> 1);           // LOCAL hd for j=0; j=1 adds 2
    const int ghd0 = colh + hdj0;

    // ---- pusher constants (tid < 128): 16-B chunk (hd, half, bgroup) ----
    const int phd   = tid & 31;
    const int phalf = (tid >> 5) & 1;
    const int pbg   = (tid >> 6) & 1;
    const uint32_t psrc = (uint32_t)(phd * 64 + phalf * 32 + pbg * 16);
    const int pgdim = colh + phd;   // global dim of this chunk
    uint32_t mbAH[CLUSTER];
    #pragma unroll
    for (int p = 0; p < CLUSTER; ++p) mbAH[p] = mapa_u32(sb + OFF_AH, (uint32_t)p);

    // ---- x staging: thread (bx, kg) handles x[gb+bx][t][4kg..4kg+3] ----
    const int bx = tid & 15;
    const int kg = tid >> 4;
    const float* xsrc = x + (size_t)(gb + bx) * S_DIM * I_DIM + 4 * kg;

    {
        float4 v = *reinterpret_cast<const float4*>(xsrc);
        float vv[4] = {v.x, v.y, v.z, v.w};
        #pragma unroll
        for (int j = 0; j < 4; ++j) {
            uint16_t hi, lo;
            bfsplit(vv[j], hi, lo);
            uint32_t o = (uint32_t)(4 * kg + j) * 32 + (uint32_t)bx * 2;
            *reinterpret_cast<uint16_t*>(smem + OFF_AX + o)        = hi;
            *reinterpret_cast<uint16_t*>(smem + OFF_AX + 2048 + o) = lo;
        }
    }
    float4 xv = *reinterpret_cast<const float4*>(xsrc + I_DIM);  // x_1 prefetch

    __syncthreads();   // weights staged — safe to hoist B fragments

    // ---- hoist ALL B (weight) fragments into registers: 20 ks x 4 x 2 halves ----
    uint32_t wbh[20][4], wbl[20][4];
    {
        const uint32_t wb = sb + OFF_W + boff;
        #pragma unroll
        for (int ks = 0; ks < 20; ++ks) {
            LDSM4T(wbh[ks][0], wbh[ks][1], wbh[ks][2], wbh[ks][3],
                   wb + (uint32_t)ks * (16 * WPITCH));
            LDSM4T(wbl[ks][0], wbl[ks][1], wbl[ks][2], wbl[ks][3],
                   wb + (uint32_t)ks * (16 * WPITCH) + WHALF);
        }
    }

    float cs[2] = {0.f, 0.f};
    float hv[2] = {0.f, 0.f};

    CLUSTER_ARRIVE();   // primes iteration-0 wait (h buffer 0 locally zeroed)

    for (int t = 0; t < S_DIM; ++t) {
        const int cur = t & 1;
        const int nxt = cur ^ 1;

        float aA[2][4], aB[2][4], aC[2][4];
        #pragma unroll
        for (int j = 0; j < 2; ++j) {
            aA[j][0] = biasA[j]; aA[j][1] = biasB[j];
            aA[j][2] = biasA[j]; aA[j][3] = biasB[j];
            aB[j][0] = 0.f; aB[j][1] = 0.f; aB[j][2] = 0.f; aB[j][3] = 0.f;
            aC[j][0] = 0.f; aC[j][1] = 0.f; aC[j][2] = 0.f; aC[j][3] = 0.f;
        }

        const uint32_t axb = sb + OFF_AX + (uint32_t)cur * AXBUF + aoff;
        const uint32_t ahb = sb + OFF_AH + (uint32_t)cur * AHBUF + aoff;

        uint32_t fah[2][4], fal[2][4];

        // ===== pre-wait phase: x-part (4 ks) + OWN h slice (h ks 0-1, rotated) =====
        LOADA(0, axb, 2048u);
        #pragma unroll
        for (int ks = 0; ks < 4; ++ks) {
            const int s = ks & 1, n = s ^ 1;
            if (ks + 1 < 4)
                LOADA(n, axb + (uint32_t)(ks + 1) * 512, 2048u);
            MMA6S(fah[s], fal[s], wbh[ks], wbl[ks]);
        }
        // own h dims occupy rotated rows 0..31 = h k-steps 0,1 (written locally at t-1)
        LOADA(0, ahb, 8192u);
        LOADA(1, ahb + 512, 8192u);
        MMA6S(fah[0], fal[0], wbh[4], wbl[4]);
        MMA6S(fah[1], fal[1], wbh[5], wbl[5]);

        // ===== join: peers' h pushes for buf cur now visible =====
        CLUSTER_WAIT();

        // ===== post-wait: h ks 2..15, register double-buffered A =====
        LOADA(0, ahb + 2 * 512, 8192u);
        #pragma unroll
        for (int ks = 2; ks < 16; ++ks) {
            const int s = ks & 1, n = s ^ 1;
            if (ks + 1 < 16)
                LOADA(n, ahb + (uint32_t)(ks + 1) * 512, 8192u);
            MMA6S(fah[s], fal[s], wbh[4 + ks], wbl[4 + ks]);
        }

        // ---- stage x_{t+1} into buf nxt; prefetch x_{t+2} ----
        if (t + 1 < S_DIM) {
            const uint32_t xo = OFF_AX + (uint32_t)nxt * AXBUF;
            float vv[4] = {xv.x, xv.y, xv.z, xv.w};
            #pragma unroll
            for (int j = 0; j < 4; ++j) {
                uint16_t hi, lo;
                bfsplit(vv[j], hi, lo);
                uint32_t o = (uint32_t)(4 * kg + j) * 32 + (uint32_t)bx * 2;
                *reinterpret_cast<uint16_t*>(smem + xo + o)        = hi;
                *reinterpret_cast<uint16_t*>(smem + xo + 2048 + o) = lo;
            }
            if (t + 2 < S_DIM)
                xv = *reinterpret_cast<const float4*>(xsrc + (size_t)(t + 2) * I_DIM);
        }

        // ---- fragment-layout epilogue: shfl-exchange gates ----
        const uint32_t bo = (uint32_t)nxt * AHBUF;
        #pragma unroll
        for (int j = 0; j < 2; ++j) {
            float e0 = aA[j][0] + aB[j][0] + aC[j][0];
            float e1 = aA[j][1] + aB[j][1] + aC[j][1];
            float e2 = aA[j][2] + aB[j][2] + aC[j][2];
            float e3 = aA[j][3] + aB[j][3] + aC[j][3];

            float s1 = odd ? e0 : e2;
            float s2 = odd ? e1 : e3;
            float r1 = __shfl_xor_sync(0xffffffffu, s1, 1);
            float r2 = __shfl_xor_sync(0xffffffffu, s2, 1);
            float gi = odd ? r1 : e0;
            float gf = odd ? r2 : e1;
            float gg = odd ? e2 : r1;
            float go = odd ? e3 : r2;

            float it = sigf(gi), ft = sigf(gf), gt = tanh_(gg), ot = sigf(go);
            cs[j] = fmaf(ft, cs[j], it * gt);
            hv[j] = ot * tanh_(cs[j]);

            const int hdl = hdj0 + 2 * j;   // local dim = rotated row in OWN panel
            uint16_t hh, hl;
            bfsplit(hv[j], hh, hl);
            // own panel slice (buf nxt) at LOCAL rotated rows 0..31
            *reinterpret_cast<uint16_t*>(smem + OFF_AH + bo + (uint32_t)(hdl * 32 + ebat * 2))        = hh;
            *reinterpret_cast<uint16_t*>(smem + OFF_AH + bo + 8192 + (uint32_t)(hdl * 32 + ebat * 2)) = hl;
            // push staging [hd local][half][b]
            *reinterpret_cast<uint16_t*>(smem + OFF_HSTG + (uint32_t)(hdl * 64 + ebat * 2))      = hh;
            *reinterpret_cast<uint16_t*>(smem + OFF_HSTG + (uint32_t)(hdl * 64 + 32 + ebat * 2)) = hl;
        }

        __syncthreads();   // Hstg + own slice + x staging complete

        // ---- compact push: 128 threads x 7 peers x 16B (peer-rotated row) ----
        if (t + 1 < S_DIM) {
            if (tid < 128) {
                uint4 v = *reinterpret_cast<const uint4*>(smem + OFF_HSTG + psrc);
                #pragma unroll
                for (int p = 0; p < CLUSTER; ++p)
                    if ((uint32_t)p != rank) {
                        int prow = (pgdim + 256 - 32 * p) & 255;
                        uint32_t pdoff = (uint32_t)(phalf * 8192 + prow * 32 + pbg * 16);
                        stc128(mbAH[p] + bo + pdoff, v);
                    }
            }
            CLUSTER_ARRIVE();   // release: remote pushes ordered before peers' wait
        }

        // hidden_seq stores AFTER the release — off the inter-CTA critical path
        {
            float* op = out + (size_t)t * (B_DIM * H_DIM) + (size_t)(gb + ebat) * H_DIM + ghd0;
            op[0] = hv[0];
            op[2] = hv[1];
        }
    }

    // ---- final h_t, c_t ----
    float* out_h = out + (size_t)S_DIM * B_DIM * H_DIM;
    float* out_c = out_h + (size_t)B_DIM * H_DIM;
    #pragma unroll
    for (int j = 0; j < 2; ++j) {
        const size_t fb = (size_t)(gb + ebat) * H_DIM + (ghd0 + 2 * j);
        out_h[fb] = hv[j];
        out_c[fb] = cs[j];
    }
}

extern "C" void kernel_launch(void* const* d_in, const int* in_sizes, int n_in,
                              void* d_out, int out_size) {
    const float* x   = (const float*)d_in[0];
    const float* w_i = (const float*)d_in[1];
    const float* u_i = (const float*)d_in[2];
    const float* b_i = (const float*)d_in[3];
    const float* w_f = (const float*)d_in[4];
    const float* u_f = (const float*)d_in[5];
    const float* b_f = (const float*)d_in[6];
    const float* w_c = (const float*)d_in[7];
    const float* u_c = (const float*)d_in[8];
    const float* b_c = (const float*)d_in[9];
    const float* w_o = (const float*)d_in[10];
    const float* u_o = (const float*)d_in[11];
    const float* b_o = (const float*)d_in[12];
    float* out = (float*)d_out;

    cudaFuncSetAttribute(lstm_hmma, cudaFuncAttributeMaxDynamicSharedMemorySize, SMEM_BYTES);

    dim3 grid((B_DIM / GBATCH) * CLUSTER);  // 16 clusters * 8 CTAs = 128
    lstm_hmma<<<grid, NTHREADS, SMEM_BYTES>>>(
        x, w_i, u_i, b_i, w_f, u_f, b_f, w_c, u_c, b_c, w_o, u_o, b_o, out);
}

// round 15
// speedup vs baseline: 1.8798x; 1.3818x over previous
#include <cuda_runtime.h>
#include <cuda_bf16.h>
#include <cstdint>

// Problem dims
#define B_DIM 256
#define S_DIM 512
#define I_DIM 64
#define H_DIM 256

#define CLUSTER 8
#define GBATCH 16
#define HSLICE 32
#define NTHREADS 256      // 8 warps

// Weights: [2 half][320 k][128 n] bf16, pitch 272B (conflict-free LDSM)
#define WPITCH 272
#define OFF_W   0
#define WHALF   (320 * WPITCH)            // 87040
// A x-panel: [2 buf][2 half][64 k][16 b] bf16
#define OFF_AX  (2 * WHALF)               // 174080
#define AXBUF   4096
// A h-panel: [2 buf][2 half][256 k][16 b] bf16
#define OFF_AH  (OFF_AX + 2 * AXBUF)      // 182272
#define AHBUF   16384
// h staging for bulk pushes: [2 half][32 hd][16 b] bf16 = 2KB (hi block, lo block)
#define OFF_HSTG (OFF_AH + 2 * AHBUF)     // 215040
// two recv mbarriers (8B each), ping-pong per h buffer
#define OFF_MBAR (OFF_HSTG + 2048)        // 217088
#define SMEM_BYTES (OFF_MBAR + 64)        // 217152

#define TX_BYTES 14336u                   // 7 peers x 2048 B per phase

__device__ __forceinline__ float sigf(float x) {
    return __fdividef(1.0f, 1.0f + __expf(-x));
}
__device__ __forceinline__ float tanh_(float x) {
    return __fdividef(2.0f, 1.0f + __expf(-2.0f * x)) - 1.0f;
}

__device__ __forceinline__ uint32_t smem_u32(const void* p) {
    uint32_t a;
    asm("{ .reg .u64 t; cvta.to.shared.u64 t, %1; cvt.u32.u64 %0, t; }" : "=r"(a) : "l"(p));
    return a;
}
__device__ __forceinline__ uint32_t mapa_u32(uint32_t addr, uint32_t rank) {
    uint32_t r;
    asm("mapa.shared::cluster.u32 %0, %1, %2;" : "=r"(r) : "r"(addr), "r"(rank));
    return r;
}
#define CLUSTER_SYNC() do { \
    asm volatile("barrier.cluster.arrive.aligned;" ::: "memory"); \
    asm volatile("barrier.cluster.wait.aligned;" ::: "memory"); \
} while (0)

// ---- mbarrier ops ----
#define MBAR_INIT(a, c) \
    asm volatile("mbarrier.init.shared.b64 [%0], %1;" :: "r"(a), "r"(c) : "memory")
#define MBAR_ARRIVE(a) \
    asm volatile("mbarrier.arrive.shared.b64 _, [%0];" :: "r"(a) : "memory")
#define MBAR_ARM_TX(a, tx) \
    asm volatile("mbarrier.arrive.expect_tx.shared.b64 _, [%0], %1;" \
                 :: "r"(a), "r"(tx) : "memory")
#define MBAR_WAIT_CLUSTER(a, ph) do { \
    uint32_t _m = (a), _p = (ph), _d; \
    asm volatile("{\n\t.reg .pred p;\n\t" \
        "mbarrier.try_wait.parity.acquire.cluster.shared::cta.b64 p, [%1], %2;\n\t" \
        "selp.b32 %0, 1, 0, p;\n\t}" : "=r"(_d) : "r"(_m), "r"(_p) : "memory"); \
    if (!_d) { \
        asm volatile("{\n\t.reg .pred P1;\n\t" \
            "WL_%=:\n\t" \
            "mbarrier.try_wait.parity.acquire.cluster.shared::cta.b64 P1, [%0], %1, 0x989680;\n\t" \
            "@P1 bra.uni WD_%=;\n\t" \
            "bra.uni WL_%=;\n\t" \
            "WD_%=:\n\t}" :: "r"(_m), "r"(_p) : "memory"); \
    } \
} while (0)

// bulk DSMEM copy: local smem -> peer smem, completion tx at peer's mbarrier
#define BULK_S2S(dst, src, bytes, mbar) \
    asm volatile("cp.async.bulk.shared::cluster.shared::cta.mbarrier::complete_tx::bytes " \
                 "[%0], [%1], %2, [%3];" \
                 :: "r"(dst), "r"(src), "r"(bytes), "r"(mbar) : "memory")
#define FENCE_PROXY_ASYNC() \
    asm volatile("fence.proxy.async.shared::cta;" ::: "memory")

#define LDSM4T(r0, r1, r2, r3, addr) \
    asm volatile("ldmatrix.sync.aligned.m8n8.x4.trans.shared.b16 {%0,%1,%2,%3}, [%4];" \
                 : "=r"(r0), "=r"(r1), "=r"(r2), "=r"(r3) : "r"(addr))

#define MMA(d0, d1, d2, d3, a0, a1, a2, a3, b0, b1) \
    asm volatile("mma.sync.aligned.m16n8k16.row.col.f32.bf16.bf16.f32 " \
                 "{%0,%1,%2,%3}, {%4,%5,%6,%7}, {%8,%9}, {%0,%1,%2,%3};" \
                 : "+f"(d0), "+f"(d1), "+f"(d2), "+f"(d3) \
                 : "r"(a0), "r"(a1), "r"(a2), "r"(a3), "r"(b0), "r"(b1))

__device__ __forceinline__ void bfsplit(float v, uint16_t& hi, uint16_t& lo) {
    __nv_bfloat16 h = __float2bfloat16(v);
    float r = v - __bfloat162float(h);
    __nv_bfloat16 l = __float2bfloat16(r);
    hi = *reinterpret_cast<uint16_t*>(&h);
    lo = *reinterpret_cast<uint16_t*>(&l);
}

// 6 MMAs per k-step, 3 INDEPENDENT accumulator chains x 2 n-tiles
#define MMA6S(AH, AL, BH, BL) do { \
    MMA(aA[0][0], aA[0][1], aA[0][2], aA[0][3], (AH)[0], (AH)[1], (AH)[2], (AH)[3], (BH)[0], (BH)[1]); \
    MMA(aB[0][0], aB[0][1], aB[0][2], aB[0][3], (AH)[0], (AH)[1], (AH)[2], (AH)[3], (BL)[0], (BL)[1]); \
    MMA(aC[0][0], aC[0][1], aC[0][2], aC[0][3], (AL)[0], (AL)[1], (AL)[2], (AL)[3], (BH)[0], (BH)[1]); \
    MMA(aA[1][0], aA[1][1], aA[1][2], aA[1][3], (AH)[0], (AH)[1], (AH)[2], (AH)[3], (BH)[2], (BH)[3]); \
    MMA(aB[1][0], aB[1][1], aB[1][2], aB[1][3], (AH)[0], (AH)[1], (AH)[2], (AH)[3], (BL)[2], (BL)[3]); \
    MMA(aC[1][0], aC[1][1], aC[1][2], aC[1][3], (AL)[0], (AL)[1], (AL)[2], (AL)[3], (BH)[2], (BH)[3]); \
} while (0)

// A-only k-step load (hi + lo halves); ALOFF = 2048 (x panel) or 8192 (h panel)
#define LOADA(S, AADDR, ALOFF) do { \
    LDSM4T(fah[S][0], fah[S][1], fah[S][2], fah[S][3], (AADDR)); \
    LDSM4T(fal[S][0], fal[S][1], fal[S][2], fal[S][3], (AADDR) + (ALOFF)); \
} while (0)

__global__ void __cluster_dims__(CLUSTER, 1, 1) __launch_bounds__(NTHREADS, 1)
lstm_hmma(const float* __restrict__ x,
          const float* __restrict__ w_i, const float* __restrict__ u_i, const float* __restrict__ b_i,
          const float* __restrict__ w_f, const float* __restrict__ u_f, const float* __restrict__ b_f,
          const float* __restrict__ w_c, const float* __restrict__ u_c, const float* __restrict__ b_c,
          const float* __restrict__ w_o, const float* __restrict__ u_o, const float* __restrict__ b_o,
          float* __restrict__ out)
{
    extern __shared__ char smem[];
    const uint32_t sb = smem_u32(smem);
    const int tid  = threadIdx.x;
    const int lane = tid & 31;
    const int warp = tid >> 5;

    uint32_t rank;
    asm("mov.u32 %0, %%cluster_ctarank;" : "=r"(rank));
    const int gb   = (blockIdx.x / CLUSTER) * GBATCH;
    const int colh = (int)rank * HSLICE;

    // ---- recv mbarriers: mbar[b] guards h buffer b ----
    const uint32_t mbar0 = sb + OFF_MBAR;
    const uint32_t mbar1 = sb + OFF_MBAR + 8;
    if (tid == 0) {
        MBAR_INIT(mbar0, 1);
        MBAR_INIT(mbar1, 1);
        MBAR_ARRIVE(mbar0);              // pre-complete phase 0 (h_0 = 0 locally)
        MBAR_ARM_TX(mbar1, TX_BYTES);    // arm buf1 phase 0 (peers' t=0 pushes)
    }

    // ---- stage weights: W[half][k][n], n = 4*hd + g, bf16 hi/lo ----
    #pragma unroll
    for (int g = 0; g < 4; ++g) {
        const float* Wsrc = (g == 0) ? w_i : (g == 1) ? w_f : (g == 2) ? w_c : w_o;
        const float* Usrc = (g == 0) ? u_i : (g == 1) ? u_f : (g == 2) ? u_c : u_o;
        for (int k = warp; k < 320; k += 8) {
            const float* src = (k < I_DIM) ? (Wsrc + (size_t)k * H_DIM)
                                           : (Usrc + (size_t)(k - I_DIM) * H_DIM);
            float v = src[colh + lane];
            uint16_t hi, lo;
            bfsplit(v, hi, lo);
            uint32_t o = (uint32_t)k * WPITCH + (uint32_t)(4 * lane + g) * 2;
            *reinterpret_cast<uint16_t*>(smem + OFF_W + o)         = hi;
            *reinterpret_cast<uint16_t*>(smem + OFF_W + WHALF + o) = lo;
        }
    }
    // zero h panel buffer 0 (both halves)
    for (int i = tid; i < AHBUF / 4; i += NTHREADS)
        reinterpret_cast<uint32_t*>(smem + OFF_AH)[i] = 0;

    // ---- lane offsets for ldmatrix.x4.trans ----
    const int lg = lane >> 3, lr = lane & 7;
    const uint32_t aoff = (uint32_t)((((lg & 2) ? 8 : 0) + lr) * 32 + ((lg & 1) ? 16 : 0));
    const uint32_t boff = (uint32_t)((((lg & 1) ? 8 : 0) + lr) * WPITCH
                                     + (16 * warp + ((lg & 2) ? 8 : 0)) * 2);

    // ---- bias constants ----
    float biasA[2], biasB[2];
    #pragma unroll
    for (int j = 0; j < 2; ++j) {
        int c0 = 16 * warp + 8 * j + 2 * (lane & 3);
        int hd0 = c0 >> 2, g0 = c0 & 3;
        const float* p0 = (g0 == 0) ? b_i : (g0 == 2) ? b_c : (g0 == 1) ? b_f : b_o;
        const float* p1 = (g0 + 1 == 1) ? b_f : (g0 + 1 == 3) ? b_o : (g0 + 1 == 2) ? b_c : b_i;
        biasA[j] = p0[colh + hd0];
        biasB[j] = p1[colh + hd0];
    }

    // ---- epilogue (fragment-layout) constants ----
    const int odd  = lane & 1;
    const int ebat = (lane >> 2) + (odd ? 8 : 0);            // owned batch (both j)
    const int hdj0 = 4 * warp + ((lane & 3) >> 1);           // hd for j=0; j=1 adds 2
    const int ghd0 = colh + hdj0;

    // ---- bulk-push constants (tid < 7): one peer per thread ----
    uint32_t pPanel = 0, pMbar = 0;
    if (tid < 7) {
        uint32_t peer = (uint32_t)((tid < (int)rank) ? tid : tid + 1);
        pPanel = mapa_u32(sb + OFF_AH, peer);
        pMbar  = mapa_u32(sb + OFF_MBAR, peer);
    }

    // ---- x staging: thread (bx, kg) handles x[gb+bx][t][4kg..4kg+3] ----
    const int bx = tid & 15;
    const int kg = tid >> 4;
    const float* xsrc = x + (size_t)(gb + bx) * S_DIM * I_DIM + 4 * kg;

    {
        float4 v = *reinterpret_cast<const float4*>(xsrc);
        float vv[4] = {v.x, v.y, v.z, v.w};
        #pragma unroll
        for (int j = 0; j < 4; ++j) {
            uint16_t hi, lo;
            bfsplit(vv[j], hi, lo);
            uint32_t o = (uint32_t)(4 * kg + j) * 32 + (uint32_t)bx * 2;
            *reinterpret_cast<uint16_t*>(smem + OFF_AX + o)        = hi;
            *reinterpret_cast<uint16_t*>(smem + OFF_AX + 2048 + o) = lo;
        }
    }
    float4 xv = *reinterpret_cast<const float4*>(xsrc + I_DIM);  // x_1 prefetch

    __syncthreads();   // weights staged — safe to hoist B fragments

    // ---- hoist ALL B (weight) fragments into registers: 20 ks x 4 x 2 halves ----
    uint32_t wbh[20][4], wbl[20][4];
    {
        const uint32_t wb = sb + OFF_W + boff;
        #pragma unroll
        for (int ks = 0; ks < 20; ++ks) {
            LDSM4T(wbh[ks][0], wbh[ks][1], wbh[ks][2], wbh[ks][3],
                   wb + (uint32_t)ks * (16 * WPITCH));
            LDSM4T(wbl[ks][0], wbl[ks][1], wbl[ks][2], wbl[ks][3],
                   wb + (uint32_t)ks * (16 * WPITCH) + WHALF);
        }
    }

    // one-time cluster sync: all mbar inits/arms + zeroed buffers visible
    CLUSTER_SYNC();

    float cs[2] = {0.f, 0.f};
    float hv[2] = {0.f, 0.f};

    for (int t = 0; t < S_DIM; ++t) {
        const int cur = t & 1;
        const int nxt = cur ^ 1;
        const uint32_t mbCur = (cur == 0) ? mbar0 : mbar1;

        float aA[2][4], aB[2][4], aC[2][4];
        #pragma unroll
        for (int j = 0; j < 2; ++j) {
            aA[j][0] = biasA[j]; aA[j][1] = biasB[j];
            aA[j][2] = biasA[j]; aA[j][3] = biasB[j];
            aB[j][0] = 0.f; aB[j][1] = 0.f; aB[j][2] = 0.f; aB[j][3] = 0.f;
            aC[j][0] = 0.f; aC[j][1] = 0.f; aC[j][2] = 0.f; aC[j][3] = 0.f;
        }

        const uint32_t axb = sb + OFF_AX + (uint32_t)cur * AXBUF + aoff;
        const uint32_t ahb = sb + OFF_AH + (uint32_t)cur * AHBUF + aoff;

        uint32_t fah[2][4], fal[2][4];

        // ===== phase 1: x-part (4 ks) — independent of peers' h, overlaps comm =====
        LOADA(0, axb, 2048u);
        #pragma unroll
        for (int ks = 0; ks < 4; ++ks) {
            const int s = ks & 1, n = s ^ 1;
            if (ks + 1 < 4)
                LOADA(n, axb + (uint32_t)(ks + 1) * 512, 2048u);
            MMA6S(fah[s], fal[s], wbh[ks], wbl[ks]);
        }

        // ===== join: wait for 14336 inbound bytes on buf cur (acquire.cluster) =====
        MBAR_WAIT_CLUSTER(mbCur, (uint32_t)((t >> 1) & 1));
        // re-arm this mbar's NEXT phase (use at t+2); ordered before our pushes
        // by the __syncthreads below; peers' arrivals require our pushes.
        if (tid == 0 && t + 2 < S_DIM)
            MBAR_ARM_TX(mbCur, TX_BYTES);

        // ===== phase 2: h-part (16 ks), register double-buffered A =====
        LOADA(0, ahb, 8192u);
        #pragma unroll
        for (int ks = 0; ks < 16; ++ks) {
            const int s = ks & 1, n = s ^ 1;
            if (ks + 1 < 16)
                LOADA(n, ahb + (uint32_t)(ks + 1) * 512, 8192u);
            MMA6S(fah[s], fal[s], wbh[4 + ks], wbl[4 + ks]);
        }

        // ---- stage x_{t+1} into buf nxt; prefetch x_{t+2} ----
        if (t + 1 < S_DIM) {
            const uint32_t xo = OFF_AX + (uint32_t)nxt * AXBUF;
            float vv[4] = {xv.x, xv.y, xv.z, xv.w};
            #pragma unroll
            for (int j = 0; j < 4; ++j) {
                uint16_t hi, lo;
                bfsplit(vv[j], hi, lo);
                uint32_t o = (uint32_t)(4 * kg + j) * 32 + (uint32_t)bx * 2;
                *reinterpret_cast<uint16_t*>(smem + xo + o)        = hi;
                *reinterpret_cast<uint16_t*>(smem + xo + 2048 + o) = lo;
            }
            if (t + 2 < S_DIM)
                xv = *reinterpret_cast<const float4*>(xsrc + (size_t)(t + 2) * I_DIM);
        }

        // ---- fragment-layout epilogue: shfl-exchange gates ----
        const uint32_t bo = (uint32_t)nxt * AHBUF;
        #pragma unroll
        for (int j = 0; j < 2; ++j) {
            float e0 = aA[j][0] + aB[j][0] + aC[j][0];
            float e1 = aA[j][1] + aB[j][1] + aC[j][1];
            float e2 = aA[j][2] + aB[j][2] + aC[j][2];
            float e3 = aA[j][3] + aB[j][3] + aC[j][3];

            float s1 = odd ? e0 : e2;
            float s2 = odd ? e1 : e3;
            float r1 = __shfl_xor_sync(0xffffffffu, s1, 1);
            float r2 = __shfl_xor_sync(0xffffffffu, s2, 1);
            float gi = odd ? r1 : e0;
            float gf = odd ? r2 : e1;
            float gg = odd ? e2 : r1;
            float go = odd ? e3 : r2;

            float it = sigf(gi), ft = sigf(gf), gt = tanh_(gg), ot = sigf(go);
            cs[j] = fmaf(ft, cs[j], it * gt);
            hv[j] = ot * tanh_(cs[j]);

            const int ghd = ghd0 + 2 * j;
            uint16_t hh, hl;
            bfsplit(hv[j], hh, hl);
            // own panel slice (buf nxt) — local write
            *reinterpret_cast<uint16_t*>(smem + OFF_AH + bo + (uint32_t)(ghd * 32 + ebat * 2))        = hh;
            *reinterpret_cast<uint16_t*>(smem + OFF_AH + bo + 8192 + (uint32_t)(ghd * 32 + ebat * 2)) = hl;
            // push staging [half][hd local][b]: hi block 1KB, lo block 1KB
            const int hdl = hdj0 + 2 * j;
            *reinterpret_cast<uint16_t*>(smem + OFF_HSTG + (uint32_t)(hdl * 32 + ebat * 2))        = hh;
            *reinterpret_cast<uint16_t*>(smem + OFF_HSTG + 1024 + (uint32_t)(hdl * 32 + ebat * 2)) = hl;
        }

        __syncthreads();   // Hstg + own slice + x staging + mbar arm complete

        // ---- bulk push: 7 threads x 1 peer x 2 copies (hi 1KB, lo 1KB) ----
        if (t + 1 < S_DIM) {
            if (tid < 7) {
                FENCE_PROXY_ASYNC();   // generic smem writes -> async proxy
                const uint32_t dstHi = pPanel + bo + (uint32_t)(colh * 32);
                const uint32_t mb    = pMbar + (uint32_t)(nxt * 8);
                BULK_S2S(dstHi,        sb + OFF_HSTG,        1024u, mb);
                BULK_S2S(dstHi + 8192, sb + OFF_HSTG + 1024, 1024u, mb);
            }
        }

        // hidden_seq stores after the pushes — off the inter-CTA critical path
        {
            float* op = out + (size_t)t * (B_DIM * H_DIM) + (size_t)(gb + ebat) * H_DIM + ghd0;
            op[0] = hv[0];
            op[2] = hv[1];
        }
    }

    // ---- final h_t, c_t ----
    float* out_h = out + (size_t)S_DIM * B_DIM * H_DIM;
    float* out_c = out_h + (size_t)B_DIM * H_DIM;
    #pragma unroll
    for (int j = 0; j < 2; ++j) {
        const size_t fb = (size_t)(gb + ebat) * H_DIM + (ghd0 + 2 * j);
        out_h[fb] = hv[j];
        out_c[fb] = cs[j];
    }

    // keep cluster resident until all peers consumed the last pushes
    CLUSTER_SYNC();
}

extern "C" void kernel_launch(void* const* d_in, const int* in_sizes, int n_in,
                              void* d_out, int out_size) {
    const float* x   = (const float*)d_in[0];
    const float* w_i = (const float*)d_in[1];
    const float* u_i = (const float*)d_in[2];
    const float* b_i = (const float*)d_in[3];
    const float* w_f = (const float*)d_in[4];
    const float* u_f = (const float*)d_in[5];
    const float* b_f = (const float*)d_in[6];
    const float* w_c = (const float*)d_in[7];
    const float* u_c = (const float*)d_in[8];
    const float* b_c = (const float*)d_in[9];
    const float* w_o = (const float*)d_in[10];
    const float* u_o = (const float*)d_in[11];
    const float* b_o = (const float*)d_in[12];
    float* out = (float*)d_out;

    cudaFuncSetAttribute(lstm_hmma, cudaFuncAttributeMaxDynamicSharedMemorySize, SMEM_BYTES);

    dim3 grid((B_DIM / GBATCH) * CLUSTER);  // 16 clusters * 8 CTAs = 128
    lstm_hmma<<<grid, NTHREADS, SMEM_BYTES>>>(
        x, w_i, u_i, b_i, w_f, u_f, b_f, w_c, u_c, b_c, w_o, u_o, b_o, out);
}